// round 1
// baseline (speedup 1.0000x reference)
#include <cuda_runtime.h>
#include <math.h>

#define D      256
#define R      16
#define N0     8192
#define L      6
#define NL     8192
#define TOTAL  (N0 + L * NL)   // 57344
#define EVAL_BLOCKS 224

// ---------------- scratch (device globals; no allocation) ----------------
__device__ float g_store[(size_t)TOTAL * D];    // node embeddings, topological
__device__ float g_P[(size_t)NL * 2 * D];       // gathered+concat parents
__device__ float g_H[(size_t)NL * D];           // hidden after relu(GEMM1)
__device__ float g_partials[EVAL_BLOCKS * 5];   // loss, posOK, negOK, posTot, negTot

// ---------------- init: store[:N0] = init_table[thax_ids] ----------------
__global__ void init_gather(const int* __restrict__ thax,
                            const float* __restrict__ table) {
    int t = blockIdx.x * blockDim.x + threadIdx.x;   // over N0*64 float4
    int row = t >> 6, c = t & 63;
    if (row < N0) {
        int tid_ = thax[row];
        const float4* src = (const float4*)(table + (size_t)tid_ * D);
        ((float4*)g_store)[(size_t)row * 64 + c] = src[c];
    }
}

// ---------------- gather parents for layer l into g_P ----------------
__global__ void gather_parents(const int* __restrict__ par /* [NL*2] */) {
    int t = blockIdx.x * blockDim.x + threadIdx.x;   // over NL*128 float4
    int row = t >> 7, c = t & 127;
    if (row < NL) {
        int which = c >> 6;       // 0: parent0, 1: parent1
        int cc = c & 63;
        int p = par[row * 2 + which];
        ((float4*)g_P)[(size_t)row * 128 + c] =
            ((const float4*)g_store)[(size_t)p * 64 + cc];
    }
}

// ---------------- grouped per-rule GEMM: C = (relu)(A @ W[r] + b[r]) ----------------
// A: [8192, K] row-major; W: [R, K, 256]; bias: [R, 256]; C: [8192, 256]
// FIRST=true : A=g_P (K=512), C=g_H, relu
// FIRST=false: A=g_H (K=256), C=g_store + (N0+layer*NL)*D, no relu
template<int K, bool FIRST>
__global__ void __launch_bounds__(256)
gemm_rule(const float* __restrict__ W, const float* __restrict__ bias, int layer) {
    const float* __restrict__ A = FIRST ? g_P : g_H;
    float* __restrict__ C = FIRST ? g_H : (g_store + (size_t)(N0 + layer * NL) * D);

    constexpr int BM = 128, BN = 128, BK = 8;
    __shared__ float As[BK][BM];
    __shared__ float Bs[BK][BN];

    const int tid = threadIdx.x;
    const int m0 = blockIdx.x * BM;
    const int n0 = blockIdx.y * BN;
    const int r  = m0 >> 9;                    // 512 rows per rule
    const float* __restrict__ Wr = W + (size_t)r * K * 256;

    const int tx = tid & 15, ty = tid >> 4;

    // A tile load mapping: 128 rows x 8 cols, float4 per half-row
    const int a_row = tid >> 1;
    const int a_seg = (tid & 1) * 4;
    // B tile load mapping: 8 k-rows x 128 cols
    const int b_kr = tid >> 5;
    const int b_nc = (tid & 31) * 4;

    float acc[8][8];
#pragma unroll
    for (int i = 0; i < 8; i++)
#pragma unroll
        for (int j = 0; j < 8; j++) acc[i][j] = 0.f;

    for (int k0 = 0; k0 < K; k0 += BK) {
        float4 av = *(const float4*)(A + (size_t)(m0 + a_row) * K + k0 + a_seg);
        As[a_seg + 0][a_row] = av.x;
        As[a_seg + 1][a_row] = av.y;
        As[a_seg + 2][a_row] = av.z;
        As[a_seg + 3][a_row] = av.w;
        *(float4*)(&Bs[b_kr][b_nc]) =
            *(const float4*)(Wr + (size_t)(k0 + b_kr) * 256 + n0 + b_nc);
        __syncthreads();

#pragma unroll
        for (int kk = 0; kk < BK; kk++) {
            float a[8], b[8];
            *(float4*)(a)     = *(const float4*)(&As[kk][ty * 4]);
            *(float4*)(a + 4) = *(const float4*)(&As[kk][64 + ty * 4]);
            *(float4*)(b)     = *(const float4*)(&Bs[kk][tx * 4]);
            *(float4*)(b + 4) = *(const float4*)(&Bs[kk][64 + tx * 4]);
#pragma unroll
            for (int i = 0; i < 8; i++)
#pragma unroll
                for (int j = 0; j < 8; j++)
                    acc[i][j] += a[i] * b[j];
        }
        __syncthreads();
    }

    // epilogue: bias (+relu), write
#pragma unroll
    for (int i = 0; i < 8; i++) {
        int m = m0 + ((i < 4) ? (ty * 4 + i) : (64 + ty * 4 + (i - 4)));
#pragma unroll
        for (int jh = 0; jh < 2; jh++) {
            int n = n0 + jh * 64 + tx * 4;
            float4 v;
            v.x = acc[i][jh * 4 + 0] + bias[r * 256 + n + 0];
            v.y = acc[i][jh * 4 + 1] + bias[r * 256 + n + 1];
            v.z = acc[i][jh * 4 + 2] + bias[r * 256 + n + 2];
            v.w = acc[i][jh * 4 + 3] + bias[r * 256 + n + 3];
            if (FIRST) {
                v.x = fmaxf(v.x, 0.f); v.y = fmaxf(v.y, 0.f);
                v.z = fmaxf(v.z, 0.f); v.w = fmaxf(v.w, 0.f);
            }
            *(float4*)(C + (size_t)m * 256 + n) = v;
        }
    }
}

// ---------------- eval + loss: per-block partial sums (deterministic) ----------------
__device__ __forceinline__ float softplusf(float x) {
    return fmaxf(x, 0.f) + log1pf(expf(-fabsf(x)));
}

__global__ void __launch_bounds__(256)
eval_partial(const float* __restrict__ pos_vals, const float* __restrict__ neg_vals,
             const float* __restrict__ eval_w, const float* __restrict__ eval_b,
             const float* __restrict__ pos_weight) {
    __shared__ float red[8][5];
    const int lane = threadIdx.x & 31, warp = threadIdx.x >> 5;
    const int gw = blockIdx.x * 8 + warp;

    float w[8];
#pragma unroll
    for (int j = 0; j < 8; j++) w[j] = eval_w[lane + 32 * j];
    const float eb = *eval_b;
    const float pw = *pos_weight;

    float loss = 0.f, posOK = 0.f, negOK = 0.f, posTot = 0.f, negTot = 0.f;

    for (int node = gw; node < TOTAL; node += EVAL_BLOCKS * 8) {
        const float* row = g_store + (size_t)node * D;
        float s = 0.f;
#pragma unroll
        for (int j = 0; j < 8; j++) s += row[lane + 32 * j] * w[j];
#pragma unroll
        for (int off = 16; off; off >>= 1) s += __shfl_xor_sync(0xffffffffu, s, off);
        if (lane == 0) {
            float x = s + eb;
            float pv = pos_vals[node], nv = neg_vals[node];
            float tot = pv + nv;
            if (tot > 0.f) {
                float tgt = pv / fmaxf(tot, 1e-9f);
                float bce = pw * tgt * softplusf(-x) + (1.f - tgt) * softplusf(x);
                loss += tot * bce;
                posTot += pv; negTot += nv;
                if (x >= 0.f) posOK += pv; else negOK += nv;
            }
        }
    }
    if (lane == 0) {
        red[warp][0] = loss; red[warp][1] = posOK; red[warp][2] = negOK;
        red[warp][3] = posTot; red[warp][4] = negTot;
    }
    __syncthreads();
    if (threadIdx.x < 5) {
        float t = 0.f;
        for (int i = 0; i < 8; i++) t += red[i][threadIdx.x];
        g_partials[blockIdx.x * 5 + threadIdx.x] = t;
    }
}

__global__ void final_reduce(float* __restrict__ out, int out_size) {
    float s[5] = {0.f, 0.f, 0.f, 0.f, 0.f};
    for (int i = threadIdx.x; i < EVAL_BLOCKS; i += 32)
#pragma unroll
        for (int c = 0; c < 5; c++) s[c] += g_partials[i * 5 + c];
#pragma unroll
    for (int c = 0; c < 5; c++)
#pragma unroll
        for (int off = 16; off; off >>= 1)
            s[c] += __shfl_xor_sync(0xffffffffu, s[c], off);
    if (threadIdx.x == 0) {
        float loss = s[0], posOK = s[1], negOK = s[2], posTot = s[3], negTot = s[4];
        float pos_rate = (posTot > 0.f) ? posOK / fmaxf(posTot, 1e-9f) : 1.f;
        float neg_rate = (negTot > 0.f) ? negOK / fmaxf(negTot, 1e-9f) : 1.f;
        if (out_size >= 1) out[0] = loss;
        if (out_size >= 2) out[1] = pos_rate;
        if (out_size >= 3) out[2] = neg_rate;
    }
}

// ---------------- launch ----------------
extern "C" void kernel_launch(void* const* d_in, const int* in_sizes, int n_in,
                              void* d_out, int out_size) {
    const int*   thax       = (const int*)  d_in[0];
    const int*   par_idx    = (const int*)  d_in[1];
    const float* pos_vals   = (const float*)d_in[2];
    const float* neg_vals   = (const float*)d_in[3];
    const float* init_table = (const float*)d_in[4];
    const float* W1         = (const float*)d_in[5];
    const float* b1         = (const float*)d_in[6];
    const float* W2         = (const float*)d_in[7];
    const float* b2         = (const float*)d_in[8];
    const float* eval_w     = (const float*)d_in[9];
    const float* eval_b     = (const float*)d_in[10];
    const float* pos_weight = (const float*)d_in[11];
    float* out = (float*)d_out;

    init_gather<<<(N0 * 64) / 256, 256>>>(thax, init_table);

    for (int l = 0; l < L; l++) {
        gather_parents<<<(NL * 128) / 256, 256>>>(par_idx + (size_t)l * NL * 2);
        gemm_rule<2 * D, true ><<<dim3(NL / 128, D / 128), 256>>>(W1, b1, l);
        gemm_rule<D,     false><<<dim3(NL / 128, D / 128), 256>>>(W2, b2, l);
    }

    eval_partial<<<EVAL_BLOCKS, 256>>>(pos_vals, neg_vals, eval_w, eval_b, pos_weight);
    final_reduce<<<1, 32>>>(out, out_size);
}

// round 3
// speedup vs baseline: 2.5845x; 2.5845x over previous
#include <cuda_runtime.h>
#include <math.h>
#include <cstdint>

#define D      256
#define R      16
#define N0     8192
#define L      6
#define NL     8192
#define TOTAL  (N0 + L * NL)   // 57344
#define EVAL_BLOCKS 224

// ---------------- scratch (device globals; no allocation) ----------------
__device__ float g_store[(size_t)TOTAL * D];       // node embeddings fp32
__device__ float g_H[(size_t)NL * D];              // hidden after relu(GEMM1)
__device__ float g_Wt1[(size_t)R * D * (2 * D)];   // W1^T: [R][256(n)][512(k)]
__device__ float g_Wt2[(size_t)R * D * D];         // W2^T: [R][256(n)][256(k)]
__device__ float g_partials[EVAL_BLOCKS * 5];

__device__ __forceinline__ uint32_t smem_to_u32(const void* p) {
    uint32_t a;
    asm("{ .reg .u64 t; cvta.to.shared.u64 t, %1; cvt.u32.u64 %0, t; }" : "=r"(a) : "l"(p));
    return a;
}

// ---------------- init: store[:N0] = init_table[thax_ids] ----------------
__global__ void init_gather(const int* __restrict__ thax,
                            const float* __restrict__ table) {
    int t = blockIdx.x * blockDim.x + threadIdx.x;
    int row = t >> 6, c = t & 63;
    if (row < N0) {
        int tid_ = thax[row];
        ((float4*)g_store)[(size_t)row * 64 + c] =
            ((const float4*)(table + (size_t)tid_ * D))[c];
    }
}

// ---------------- weight transpose: W[R][K][256] -> Wt[R][256][K] ----------------
template<int K, bool FIRST>
__global__ void transpose_w(const float* __restrict__ W) {
    __shared__ float tile[32][33];
    float* Wt = FIRST ? g_Wt1 : g_Wt2;
    int r = blockIdx.z;
    int k0 = blockIdx.x * 32, nb = blockIdx.y * 32;
    int tx = threadIdx.x, ty = threadIdx.y;
    const float* Wr = W + (size_t)r * K * D;
    float* Wtr = Wt + (size_t)r * D * K;
#pragma unroll
    for (int i = ty; i < 32; i += 8)
        tile[i][tx] = Wr[(size_t)(k0 + i) * D + nb + tx];
    __syncthreads();
#pragma unroll
    for (int i = ty; i < 32; i += 8)
        Wtr[(size_t)(nb + i) * K + k0 + tx] = tile[tx][i];
}

// ---------------- tensor-core grouped GEMM via mma.sync tf32 ----------------
// FIRST: g_H = relu(gather(par -> g_store) @ W1[r] + b1), K=512
// else : g_store[N0+l*NL ...] = g_H @ W2[r] + b2,          K=256
// CTA: 256 threads (8 warps as 2x4), tile BM=64 x BN=256 x BK=16, 3-stage cp.async.
// Warp tile 32x64 = 2(m16) x 8(n8) mma tiles. Smem row stride 20 floats
// (conflict-free fragment loads, 80B = 16B-aligned cp.async rows).
template<int K, bool FIRST>
__global__ void __launch_bounds__(256, 1)
gemm_mma(const float* __restrict__ bias, const int* __restrict__ par, int layer) {
    constexpr int NIT = K / 16;
    constexpr int NS  = 3;
    constexpr int AST = 64 * 20;          // A stage floats
    constexpr int BST = 256 * 20;         // B stage floats
    constexpr int STG = AST + BST;
    extern __shared__ float smf[];

    const int tid  = threadIdx.x;
    const int wid  = tid >> 5, lane = tid & 31;
    const int g    = lane >> 2, t4 = lane & 3;
    const int warp_m = wid >> 2, warp_n = wid & 3;
    const int m0 = blockIdx.x * 64;
    const int r  = m0 >> 9;

    // loader-role constants
    const int lrow = tid >> 2;            // A tile row 0..63
    const int lkc  = (tid & 3) * 4;       // A col chunk base
    const float* asrc0;
    const float* asrc1 = nullptr;
    if (FIRST) {
        int m = m0 + lrow;
        int p0 = par[2 * m], p1 = par[2 * m + 1];
        asrc0 = g_store + (size_t)p0 * D;
        asrc1 = g_store + (size_t)p1 * D;
    } else {
        asrc0 = g_H + (size_t)(m0 + lrow) * D;
    }
    const float* Wtr = (FIRST ? g_Wt1 : g_Wt2) + (size_t)r * D * K;
    const uint32_t smem_base = smem_to_u32(smf);

    auto issue = [&](int stage) {
        const int buf = stage % NS;
        const int k0  = stage * 16;
        // A: one 16B chunk per thread (64 rows x 16 cols)
        const float* s;
        int gk = k0 + lkc;
        if (FIRST) s = (gk < D) ? (asrc0 + gk) : (asrc1 + gk - D);
        else       s = asrc0 + gk;
        uint32_t da = smem_base + (uint32_t)(buf * STG + lrow * 20 + lkc) * 4u;
        asm volatile("cp.async.cg.shared.global [%0], [%1], 16;" :: "r"(da), "l"(s));
        // B: four 16B chunks per thread (256 rows x 16 cols)
#pragma unroll
        for (int j = 0; j < 4; j++) {
            int c = tid + 256 * j;
            int row = c >> 2, kc = (c & 3) * 4;
            const float* sb = Wtr + (size_t)row * K + k0 + kc;
            uint32_t db = smem_base + (uint32_t)(buf * STG + AST + row * 20 + kc) * 4u;
            asm volatile("cp.async.cg.shared.global [%0], [%1], 16;" :: "r"(db), "l"(sb));
        }
    };

    float acc[2][8][4];
#pragma unroll
    for (int mt = 0; mt < 2; mt++)
#pragma unroll
        for (int nt = 0; nt < 8; nt++)
#pragma unroll
            for (int c = 0; c < 4; c++) acc[mt][nt][c] = 0.f;

    issue(0); asm volatile("cp.async.commit_group;");
    issue(1); asm volatile("cp.async.commit_group;");

    for (int it = 0; it < NIT; it++) {
        if (it + 2 < NIT) issue(it + 2);
        asm volatile("cp.async.commit_group;");
        asm volatile("cp.async.wait_group 2;");
        __syncthreads();

        const float* As = smf + (it % NS) * STG;
        const float* Bs = As + AST;
#pragma unroll
        for (int kk = 0; kk < 16; kk += 8) {
            uint32_t a[2][4], b[8][2];
#pragma unroll
            for (int mt = 0; mt < 2; mt++) {
                int mr = warp_m * 32 + mt * 16;
                a[mt][0] = __float_as_uint(As[(mr + g)     * 20 + kk + t4]);
                a[mt][1] = __float_as_uint(As[(mr + g + 8) * 20 + kk + t4]);
                a[mt][2] = __float_as_uint(As[(mr + g)     * 20 + kk + t4 + 4]);
                a[mt][3] = __float_as_uint(As[(mr + g + 8) * 20 + kk + t4 + 4]);
            }
#pragma unroll
            for (int nt = 0; nt < 8; nt++) {
                int nc = warp_n * 64 + nt * 8;
                b[nt][0] = __float_as_uint(Bs[(nc + g) * 20 + kk + t4]);
                b[nt][1] = __float_as_uint(Bs[(nc + g) * 20 + kk + t4 + 4]);
            }
#pragma unroll
            for (int mt = 0; mt < 2; mt++)
#pragma unroll
                for (int nt = 0; nt < 8; nt++) {
                    asm volatile(
                        "mma.sync.aligned.m16n8k8.row.col.f32.tf32.tf32.f32 "
                        "{%0,%1,%2,%3}, {%4,%5,%6,%7}, {%8,%9}, {%0,%1,%2,%3};"
                        : "+f"(acc[mt][nt][0]), "+f"(acc[mt][nt][1]),
                          "+f"(acc[mt][nt][2]), "+f"(acc[mt][nt][3])
                        : "r"(a[mt][0]), "r"(a[mt][1]), "r"(a[mt][2]), "r"(a[mt][3]),
                          "r"(b[nt][0]), "r"(b[nt][1]));
                }
        }
        __syncthreads();
    }

    // epilogue: bias (+relu), direct gmem stores (float2 per c-pair)
    float* Cbase = FIRST ? g_H : (g_store + (size_t)(N0 + layer * NL) * D);
    const float* brow = bias + r * D;
#pragma unroll
    for (int mt = 0; mt < 2; mt++) {
        int mr0 = m0 + warp_m * 32 + mt * 16 + g;
#pragma unroll
        for (int nt = 0; nt < 8; nt++) {
            int col = warp_n * 64 + nt * 8 + 2 * t4;
            float bx = brow[col], by = brow[col + 1];
            float2 v0, v1;
            v0.x = acc[mt][nt][0] + bx;  v0.y = acc[mt][nt][1] + by;
            v1.x = acc[mt][nt][2] + bx;  v1.y = acc[mt][nt][3] + by;
            if (FIRST) {
                v0.x = fmaxf(v0.x, 0.f); v0.y = fmaxf(v0.y, 0.f);
                v1.x = fmaxf(v1.x, 0.f); v1.y = fmaxf(v1.y, 0.f);
            }
            *(float2*)(Cbase + (size_t)mr0 * D + col)       = v0;
            *(float2*)(Cbase + (size_t)(mr0 + 8) * D + col) = v1;
        }
    }
}

// ---------------- eval + loss (deterministic two-stage reduction) ----------------
__device__ __forceinline__ float softplusf(float x) {
    return fmaxf(x, 0.f) + log1pf(expf(-fabsf(x)));
}

__global__ void __launch_bounds__(256)
eval_partial(const float* __restrict__ pos_vals, const float* __restrict__ neg_vals,
             const float* __restrict__ eval_w, const float* __restrict__ eval_b,
             const float* __restrict__ pos_weight) {
    __shared__ float red[8][5];
    const int lane = threadIdx.x & 31, warp = threadIdx.x >> 5;
    const int gw = blockIdx.x * 8 + warp;

    float w[8];
#pragma unroll
    for (int j = 0; j < 8; j++) w[j] = eval_w[lane + 32 * j];
    const float eb = *eval_b;
    const float pw = *pos_weight;

    float loss = 0.f, posOK = 0.f, negOK = 0.f, posTot = 0.f, negTot = 0.f;

    for (int node = gw; node < TOTAL; node += EVAL_BLOCKS * 8) {
        const float* row = g_store + (size_t)node * D;
        float s = 0.f;
#pragma unroll
        for (int j = 0; j < 8; j++) s += row[lane + 32 * j] * w[j];
#pragma unroll
        for (int off = 16; off; off >>= 1) s += __shfl_xor_sync(0xffffffffu, s, off);
        if (lane == 0) {
            float x = s + eb;
            float pv = pos_vals[node], nv = neg_vals[node];
            float tot = pv + nv;
            if (tot > 0.f) {
                float tgt = pv / fmaxf(tot, 1e-9f);
                float bce = pw * tgt * softplusf(-x) + (1.f - tgt) * softplusf(x);
                loss += tot * bce;
                posTot += pv; negTot += nv;
                if (x >= 0.f) posOK += pv; else negOK += nv;
            }
        }
    }
    if (lane == 0) {
        red[warp][0] = loss; red[warp][1] = posOK; red[warp][2] = negOK;
        red[warp][3] = posTot; red[warp][4] = negTot;
    }
    __syncthreads();
    if (threadIdx.x < 5) {
        float t = 0.f;
        for (int i = 0; i < 8; i++) t += red[i][threadIdx.x];
        g_partials[blockIdx.x * 5 + threadIdx.x] = t;
    }
}

__global__ void final_reduce(float* __restrict__ out, int out_size) {
    float s[5] = {0.f, 0.f, 0.f, 0.f, 0.f};
    for (int i = threadIdx.x; i < EVAL_BLOCKS; i += 32)
#pragma unroll
        for (int c = 0; c < 5; c++) s[c] += g_partials[i * 5 + c];
#pragma unroll
    for (int c = 0; c < 5; c++)
#pragma unroll
        for (int off = 16; off; off >>= 1)
            s[c] += __shfl_xor_sync(0xffffffffu, s[c], off);
    if (threadIdx.x == 0) {
        float loss = s[0], posOK = s[1], negOK = s[2], posTot = s[3], negTot = s[4];
        float pos_rate = (posTot > 0.f) ? posOK / fmaxf(posTot, 1e-9f) : 1.f;
        float neg_rate = (negTot > 0.f) ? negOK / fmaxf(negTot, 1e-9f) : 1.f;
        if (out_size >= 1) out[0] = loss;
        if (out_size >= 2) out[1] = pos_rate;
        if (out_size >= 3) out[2] = neg_rate;
    }
}

// ---------------- launch ----------------
extern "C" void kernel_launch(void* const* d_in, const int* in_sizes, int n_in,
                              void* d_out, int out_size) {
    const int*   thax       = (const int*)  d_in[0];
    const int*   par_idx    = (const int*)  d_in[1];
    const float* pos_vals   = (const float*)d_in[2];
    const float* neg_vals   = (const float*)d_in[3];
    const float* init_table = (const float*)d_in[4];
    const float* W1         = (const float*)d_in[5];
    const float* b1         = (const float*)d_in[6];
    const float* W2         = (const float*)d_in[7];
    const float* b2         = (const float*)d_in[8];
    const float* eval_w     = (const float*)d_in[9];
    const float* eval_b     = (const float*)d_in[10];
    const float* pos_weight = (const float*)d_in[11];
    float* out = (float*)d_out;

    constexpr int SMEM_BYTES = 3 * (64 * 20 + 256 * 20) * 4;   // 76800
    static bool attr_set = false;
    cudaFuncSetAttribute(gemm_mma<2 * D, true>,
                         cudaFuncAttributeMaxDynamicSharedMemorySize, SMEM_BYTES);
    cudaFuncSetAttribute(gemm_mma<D, false>,
                         cudaFuncAttributeMaxDynamicSharedMemorySize, SMEM_BYTES);
    (void)attr_set;

    init_gather<<<(N0 * 64) / 256, 256>>>(thax, init_table);
    transpose_w<2 * D, true ><<<dim3(2 * D / 32, D / 32, R), dim3(32, 8)>>>(W1);
    transpose_w<D,     false><<<dim3(D / 32,     D / 32, R), dim3(32, 8)>>>(W2);

    for (int l = 0; l < L; l++) {
        gemm_mma<2 * D, true ><<<NL / 64, 256, SMEM_BYTES>>>(
            b1, par_idx + (size_t)l * NL * 2, l);
        gemm_mma<D,     false><<<NL / 64, 256, SMEM_BYTES>>>(
            b2, nullptr, l);
    }

    eval_partial<<<EVAL_BLOCKS, 256>>>(pos_vals, neg_vals, eval_w, eval_b, pos_weight);
    final_reduce<<<1, 32>>>(out, out_size);
}

// round 4
// speedup vs baseline: 2.7889x; 1.0791x over previous
#include <cuda_runtime.h>
#include <math.h>
#include <cstdint>

#define D      256
#define R      16
#define N0     8192
#define L      6
#define NL     8192
#define TOTAL  (N0 + L * NL)   // 57344
#define EVAL_BLOCKS 224

#define K1 512
#define K2 256
#define NIT1 (K1 / 16)   // 32
#define NIT2 (K2 / 16)   // 16
#define NS 4

// smem layout (in floats)
#define OFF_A1 0                       // 4 x (64*16)   = 4096
#define OFF_B1 4096                    // 4 x (256*16)  = 16384
#define OFF_B2 20480                   // 4 x (256*16)  = 16384
#define OFF_H  36864                   // 64 x 272      = 17408
#define SMEM_FLOATS 54272
#define SMEM_BYTES (SMEM_FLOATS * 4)   // 217088

// ---------------- scratch (device globals; no allocation) ----------------
__device__ float g_store[(size_t)TOTAL * D];       // node embeddings fp32
__device__ float g_Wt1[(size_t)R * D * K1];        // W1^T, k-interleaved: [R][n][K]
__device__ float g_Wt2[(size_t)R * D * K2];        // W2^T, k-interleaved
__device__ float g_partials[EVAL_BLOCKS * 5];

__device__ __forceinline__ uint32_t smem_to_u32(const void* p) {
    uint32_t a;
    asm("{ .reg .u64 t; cvta.to.shared.u64 t, %1; cvt.u32.u64 %0, t; }" : "=r"(a) : "l"(p));
    return a;
}

// ---------------- init: store[:N0] = init_table[thax_ids] ----------------
__global__ void init_gather(const int* __restrict__ thax,
                            const float* __restrict__ table) {
    int t = blockIdx.x * blockDim.x + threadIdx.x;
    int row = t >> 6, c = t & 63;
    if (row < N0) {
        int tid_ = thax[row];
        ((float4*)g_store)[(size_t)row * 64 + c] =
            ((const float4*)(table + (size_t)tid_ * D))[c];
    }
}

// ---------------- weight transpose + k-interleave ----------------
// W[R][K][256] -> Wt[R][256(n)][K storage], storage pos within each 16-k group:
// pos(k) = (k&3)*4 + (k>>2)  (so a thread's k = t4+4j values are contiguous)
template<int K, bool FIRST>
__global__ void transpose_w(const float* __restrict__ W) {
    __shared__ float tile[32][33];
    float* Wt = FIRST ? g_Wt1 : g_Wt2;
    int r = blockIdx.z;
    int k0 = blockIdx.x * 32, nb = blockIdx.y * 32;
    int tx = threadIdx.x, ty = threadIdx.y;
    const float* Wr = W + (size_t)r * K * D;
    float* Wtr = Wt + (size_t)r * D * K;
#pragma unroll
    for (int i = ty; i < 32; i += 8)
        tile[i][tx] = Wr[(size_t)(k0 + i) * D + nb + tx];
    __syncthreads();
    int gl = tx >> 4, p = tx & 15;
    int kl = (p & 3) * 4 + (p >> 2);          // inverse of pos()
#pragma unroll
    for (int i = ty; i < 32; i += 8)
        Wtr[(size_t)(nb + i) * K + k0 + gl * 16 + p] = tile[gl * 16 + kl][i];
}

// ---------------- fused layer kernel ----------------
// GEMM1: Htile(smem) = relu(gather(par->g_store)[64xK1] @ W1[r] + b1)
// GEMM2: g_store[N0+l*NL + m] = Htile @ W2[r] + b2
// CTA: 256 thr, 8 warps (2x4), warp tile 32x64, BM=64, BN=256.
__global__ void __launch_bounds__(256, 1)
layer_fused(const float* __restrict__ b1, const float* __restrict__ b2,
            const int* __restrict__ par, int layer) {
    extern __shared__ float smf[];
    const uint32_t smem_u32 = smem_to_u32(smf);

    const int tid  = threadIdx.x;
    const int lane = tid & 31;
    const int wid  = tid >> 5;
    const int g    = lane >> 2, t4 = lane & 3;
    const int warp_m = wid >> 2, warp_n = wid & 3;
    const int m0 = blockIdx.x * 64;
    const int r  = m0 >> 9;

    // ---- loader thread constants ----
    const int lrow = tid >> 2;       // A row 0..63
    const int lsub = tid & 3;        // 4-float chunk within 16
    int p0 = par[2 * (m0 + lrow)];
    int p1 = par[2 * (m0 + lrow) + 1];
    const float* asrc0 = g_store + (size_t)p0 * D;
    const float* asrc1 = g_store + (size_t)p1 * D;
    const float* W1r = g_Wt1 + (size_t)r * D * K1;
    const float* W2r = g_Wt2 + (size_t)r * D * K2;

    auto loadA = [&](int s) -> float4 {
        int gk = s * 16 + lsub * 4;
        const float* src = (gk < D) ? (asrc0 + gk) : (asrc1 + gk - D);
        return *(const float4*)src;
    };
    auto stsA = [&](int s, float4 v) {
        float* dst = smf + OFF_A1 + (s & 3) * 1024 + lrow * 16 + lsub;
        dst[0]  = v.x;   // storage pos = i*4 + lsub for component i
        dst[4]  = v.y;
        dst[8]  = v.z;
        dst[12] = v.w;
    };
    auto issueB = [&](int bufFloats, const float* Wtr, int Kd, int s) {
#pragma unroll
        for (int j = 0; j < 4; j++) {
            int c = tid + 256 * j;
            int row = c >> 2, sub = c & 3;
            const float* src = Wtr + (size_t)row * Kd + s * 16 + sub * 4;
            uint32_t dst = smem_u32 +
                (uint32_t)(bufFloats + (s & 3) * 4096 + row * 16 + sub * 4) * 4u;
            asm volatile("cp.async.cg.shared.global [%0], [%1], 16;" :: "r"(dst), "l"(src));
        }
    };

    float acc[2][8][4];
#pragma unroll
    for (int mt = 0; mt < 2; mt++)
#pragma unroll
        for (int nt = 0; nt < 8; nt++)
#pragma unroll
            for (int c = 0; c < 4; c++) acc[mt][nt][c] = 0.f;

    // fragment compute on one 16-k stage. Abase points at (warp rows, t4 chunk).
    auto tile_mma = [&](const float* Abase, int astr, const float* Bbase) {
        float4 Ar[2][2];
        float4 Br[8];
#pragma unroll
        for (int mt = 0; mt < 2; mt++)
#pragma unroll
            for (int h = 0; h < 2; h++)
                Ar[mt][h] = *(const float4*)(Abase + (mt * 16 + h * 8) * astr);
#pragma unroll
        for (int nt = 0; nt < 8; nt++)
            Br[nt] = *(const float4*)(Bbase + nt * 8 * 16);
        // kk = 0 half: components x (k=t4), y (k=t4+4)
        // kk = 8 half: components z (k=t4+8), w (k=t4+12)
#pragma unroll
        for (int h = 0; h < 2; h++) {
#pragma unroll
            for (int mt = 0; mt < 2; mt++) {
                uint32_t a0, a1, a2, a3;
                if (h == 0) {
                    a0 = __float_as_uint(Ar[mt][0].x); a1 = __float_as_uint(Ar[mt][1].x);
                    a2 = __float_as_uint(Ar[mt][0].y); a3 = __float_as_uint(Ar[mt][1].y);
                } else {
                    a0 = __float_as_uint(Ar[mt][0].z); a1 = __float_as_uint(Ar[mt][1].z);
                    a2 = __float_as_uint(Ar[mt][0].w); a3 = __float_as_uint(Ar[mt][1].w);
                }
#pragma unroll
                for (int nt = 0; nt < 8; nt++) {
                    uint32_t b0, b1;
                    if (h == 0) { b0 = __float_as_uint(Br[nt].x); b1 = __float_as_uint(Br[nt].y); }
                    else        { b0 = __float_as_uint(Br[nt].z); b1 = __float_as_uint(Br[nt].w); }
                    asm volatile(
                        "mma.sync.aligned.m16n8k8.row.col.f32.tf32.tf32.f32 "
                        "{%0,%1,%2,%3}, {%4,%5,%6,%7}, {%8,%9}, {%0,%1,%2,%3};"
                        : "+f"(acc[mt][nt][0]), "+f"(acc[mt][nt][1]),
                          "+f"(acc[mt][nt][2]), "+f"(acc[mt][nt][3])
                        : "r"(a0), "r"(a1), "r"(a2), "r"(a3), "r"(b0), "r"(b1));
                }
            }
        }
    };

    // ================= GEMM1 =================
    {
        float4 a0 = loadA(0), a1 = loadA(1), a2 = loadA(2);
        issueB(OFF_B1, W1r, K1, 0); asm volatile("cp.async.commit_group;");
        issueB(OFF_B1, W1r, K1, 1); asm volatile("cp.async.commit_group;");
        issueB(OFF_B1, W1r, K1, 2); asm volatile("cp.async.commit_group;");
        stsA(0, a0); stsA(1, a1); stsA(2, a2);
        float4 aReg = loadA(3);

        for (int it = 0; it < NIT1; it++) {
            asm volatile("cp.async.wait_group 2;");
            __syncthreads();
            if (it + 3 < NIT1) {
                issueB(OFF_B1, W1r, K1, it + 3);
                asm volatile("cp.async.commit_group;");
                stsA(it + 3, aReg);
                if (it + 4 < NIT1) aReg = loadA(it + 4);
            }
            const float* Abase = smf + OFF_A1 + (it & 3) * 1024
                               + (warp_m * 32 + g) * 16 + t4 * 4;
            const float* Bbase = smf + OFF_B1 + (it & 3) * 4096
                               + (warp_n * 64 + g) * 16 + t4 * 4;
            tile_mma(Abase, 16, Bbase);
        }
    }

    // ---- prefetch GEMM2 B stages (hidden behind H epilogue) ----
    issueB(OFF_B2, W2r, K2, 0); asm volatile("cp.async.commit_group;");
    issueB(OFF_B2, W2r, K2, 1); asm volatile("cp.async.commit_group;");
    issueB(OFF_B2, W2r, K2, 2); asm volatile("cp.async.commit_group;");

    // ---- H epilogue: bias1 + relu, scatter into interleaved H (stride 272) ----
    {
        const float* b1r = b1 + r * D;
#pragma unroll
        for (int mt = 0; mt < 2; mt++) {
            int rA = warp_m * 32 + mt * 16 + g;
            int rB = rA + 8;
#pragma unroll
            for (int nt = 0; nt < 8; nt++) {
                int col0 = warp_n * 64 + nt * 8 + 2 * t4;
                int col1 = col0 + 1;
                float bx = b1r[col0], by = b1r[col1];
                int q0 = (col0 >> 4) * 16 + (col0 & 3) * 4 + ((col0 & 15) >> 2);
                int q1 = (col1 >> 4) * 16 + (col1 & 3) * 4 + ((col1 & 15) >> 2);
                smf[OFF_H + rA * 272 + q0] = fmaxf(acc[mt][nt][0] + bx, 0.f);
                smf[OFF_H + rA * 272 + q1] = fmaxf(acc[mt][nt][1] + by, 0.f);
                smf[OFF_H + rB * 272 + q0] = fmaxf(acc[mt][nt][2] + bx, 0.f);
                smf[OFF_H + rB * 272 + q1] = fmaxf(acc[mt][nt][3] + by, 0.f);
            }
        }
    }
    __syncthreads();

    // ================= GEMM2 (A = H resident in smem) =================
#pragma unroll
    for (int mt = 0; mt < 2; mt++)
#pragma unroll
        for (int nt = 0; nt < 8; nt++)
#pragma unroll
            for (int c = 0; c < 4; c++) acc[mt][nt][c] = 0.f;

    for (int it = 0; it < NIT2; it++) {
        asm volatile("cp.async.wait_group 2;");
        __syncthreads();
        if (it + 3 < NIT2) {
            issueB(OFF_B2, W2r, K2, it + 3);
            asm volatile("cp.async.commit_group;");
        }
        const float* Abase = smf + OFF_H + (warp_m * 32 + g) * 272 + it * 16 + t4 * 4;
        const float* Bbase = smf + OFF_B2 + (it & 3) * 4096
                           + (warp_n * 64 + g) * 16 + t4 * 4;
        tile_mma(Abase, 272, Bbase);
    }

    // ---- final epilogue: bias2, write g_store ----
    {
        float* Cbase = g_store + (size_t)(N0 + layer * NL) * D;
        const float* b2r = b2 + r * D;
#pragma unroll
        for (int mt = 0; mt < 2; mt++) {
            int mr0 = m0 + warp_m * 32 + mt * 16 + g;
#pragma unroll
            for (int nt = 0; nt < 8; nt++) {
                int col = warp_n * 64 + nt * 8 + 2 * t4;
                float bx = b2r[col], by = b2r[col + 1];
                float2 v0, v1;
                v0.x = acc[mt][nt][0] + bx;  v0.y = acc[mt][nt][1] + by;
                v1.x = acc[mt][nt][2] + bx;  v1.y = acc[mt][nt][3] + by;
                *(float2*)(Cbase + (size_t)mr0 * D + col)       = v0;
                *(float2*)(Cbase + (size_t)(mr0 + 8) * D + col) = v1;
            }
        }
    }
}

// ---------------- eval + loss (deterministic two-stage reduction) ----------------
__device__ __forceinline__ float softplusf(float x) {
    return fmaxf(x, 0.f) + log1pf(expf(-fabsf(x)));
}

__global__ void __launch_bounds__(256)
eval_partial(const float* __restrict__ pos_vals, const float* __restrict__ neg_vals,
             const float* __restrict__ eval_w, const float* __restrict__ eval_b,
             const float* __restrict__ pos_weight) {
    __shared__ float red[8][5];
    const int lane = threadIdx.x & 31, warp = threadIdx.x >> 5;
    const int gw = blockIdx.x * 8 + warp;

    float w[8];
#pragma unroll
    for (int j = 0; j < 8; j++) w[j] = eval_w[lane + 32 * j];
    const float eb = *eval_b;
    const float pw = *pos_weight;

    float loss = 0.f, posOK = 0.f, negOK = 0.f, posTot = 0.f, negTot = 0.f;

    for (int node = gw; node < TOTAL; node += EVAL_BLOCKS * 8) {
        const float* row = g_store + (size_t)node * D;
        float s = 0.f;
#pragma unroll
        for (int j = 0; j < 8; j++) s += row[lane + 32 * j] * w[j];
#pragma unroll
        for (int off = 16; off; off >>= 1) s += __shfl_xor_sync(0xffffffffu, s, off);
        if (lane == 0) {
            float x = s + eb;
            float pv = pos_vals[node], nv = neg_vals[node];
            float tot = pv + nv;
            if (tot > 0.f) {
                float tgt = pv / fmaxf(tot, 1e-9f);
                float bce = pw * tgt * softplusf(-x) + (1.f - tgt) * softplusf(x);
                loss += tot * bce;
                posTot += pv; negTot += nv;
                if (x >= 0.f) posOK += pv; else negOK += nv;
            }
        }
    }
    if (lane == 0) {
        red[warp][0] = loss; red[warp][1] = posOK; red[warp][2] = negOK;
        red[warp][3] = posTot; red[warp][4] = negTot;
    }
    __syncthreads();
    if (threadIdx.x < 5) {
        float t = 0.f;
        for (int i = 0; i < 8; i++) t += red[i][threadIdx.x];
        g_partials[blockIdx.x * 5 + threadIdx.x] = t;
    }
}

__global__ void final_reduce(float* __restrict__ out, int out_size) {
    float s[5] = {0.f, 0.f, 0.f, 0.f, 0.f};
    for (int i = threadIdx.x; i < EVAL_BLOCKS; i += 32)
#pragma unroll
        for (int c = 0; c < 5; c++) s[c] += g_partials[i * 5 + c];
#pragma unroll
    for (int c = 0; c < 5; c++)
#pragma unroll
        for (int off = 16; off; off >>= 1)
            s[c] += __shfl_xor_sync(0xffffffffu, s[c], off);
    if (threadIdx.x == 0) {
        float loss = s[0], posOK = s[1], negOK = s[2], posTot = s[3], negTot = s[4];
        float pos_rate = (posTot > 0.f) ? posOK / fmaxf(posTot, 1e-9f) : 1.f;
        float neg_rate = (negTot > 0.f) ? negOK / fmaxf(negTot, 1e-9f) : 1.f;
        if (out_size >= 1) out[0] = loss;
        if (out_size >= 2) out[1] = pos_rate;
        if (out_size >= 3) out[2] = neg_rate;
    }
}

// ---------------- launch ----------------
extern "C" void kernel_launch(void* const* d_in, const int* in_sizes, int n_in,
                              void* d_out, int out_size) {
    const int*   thax       = (const int*)  d_in[0];
    const int*   par_idx    = (const int*)  d_in[1];
    const float* pos_vals   = (const float*)d_in[2];
    const float* neg_vals   = (const float*)d_in[3];
    const float* init_table = (const float*)d_in[4];
    const float* W1         = (const float*)d_in[5];
    const float* b1         = (const float*)d_in[6];
    const float* W2         = (const float*)d_in[7];
    const float* b2         = (const float*)d_in[8];
    const float* eval_w     = (const float*)d_in[9];
    const float* eval_b     = (const float*)d_in[10];
    const float* pos_weight = (const float*)d_in[11];
    float* out = (float*)d_out;

    cudaFuncSetAttribute(layer_fused,
                         cudaFuncAttributeMaxDynamicSharedMemorySize, SMEM_BYTES);

    init_gather<<<(N0 * 64) / 256, 256>>>(thax, init_table);
    transpose_w<K1, true ><<<dim3(K1 / 32, D / 32, R), dim3(32, 8)>>>(W1);
    transpose_w<K2, false><<<dim3(K2 / 32, D / 32, R), dim3(32, 8)>>>(W2);

    for (int l = 0; l < L; l++) {
        layer_fused<<<NL / 64, 256, SMEM_BYTES>>>(
            b1, b2, par_idx + (size_t)l * NL * 2, l);
    }

    eval_partial<<<EVAL_BLOCKS, 256>>>(pos_vals, neg_vals, eval_w, eval_b, pos_weight);
    final_reduce<<<1, 32>>>(out, out_size);
}

// round 5
// speedup vs baseline: 2.8564x; 1.0242x over previous
#include <cuda_runtime.h>
#include <math.h>
#include <cstdint>

#define D      256
#define R      16
#define N0     8192
#define L      6
#define NL     8192
#define TOTAL  (N0 + L * NL)   // 57344
#define EVAL_BLOCKS 224

#define K1 512
#define K2 256
#define NIT1 (K1 / 16)   // 32
#define NIT2 (K2 / 16)   // 16

// smem layout (in floats)
#define OFF_A1 0                       // 4 x (64*16)   = 4096
#define OFF_B1 4096                    // 4 x (256*16)  = 16384
#define OFF_B2 20480                   // 4 x (256*16)  = 16384
#define OFF_H  36864                   // 64 x 272      = 17408
#define SMEM_FLOATS 54272
#define SMEM_BYTES (SMEM_FLOATS * 4)   // 217088

// ---------------- scratch (device globals; no allocation) ----------------
__device__ float g_store[(size_t)TOTAL * D];       // node embeddings fp32
__device__ float g_Wt1[(size_t)R * D * K1];        // W1^T, k-interleaved: [R][n][K]
__device__ float g_Wt2[(size_t)R * D * K2];        // W2^T, k-interleaved
__device__ float g_partials[EVAL_BLOCKS * 5];

__device__ __forceinline__ uint32_t smem_to_u32(const void* p) {
    uint32_t a;
    asm("{ .reg .u64 t; cvta.to.shared.u64 t, %1; cvt.u32.u64 %0, t; }" : "=r"(a) : "l"(p));
    return a;
}

// ---------------- init: store[:N0] = init_table[thax_ids] ----------------
__global__ void init_gather(const int* __restrict__ thax,
                            const float* __restrict__ table) {
    int t = blockIdx.x * blockDim.x + threadIdx.x;
    int row = t >> 6, c = t & 63;
    if (row < N0) {
        int tid_ = thax[row];
        ((float4*)g_store)[(size_t)row * 64 + c] =
            ((const float4*)(table + (size_t)tid_ * D))[c];
    }
}

// ---------------- weight transpose + k-interleave ----------------
// W[R][K][256] -> Wt[R][256(n)][K storage], pos within each 16-k group:
// pos(k) = (k&3)*4 + (k>>2)
template<int K, bool FIRST>
__global__ void transpose_w(const float* __restrict__ W) {
    __shared__ float tile[32][33];
    float* Wt = FIRST ? g_Wt1 : g_Wt2;
    int r = blockIdx.z;
    int k0 = blockIdx.x * 32, nb = blockIdx.y * 32;
    int tx = threadIdx.x, ty = threadIdx.y;
    const float* Wr = W + (size_t)r * K * D;
    float* Wtr = Wt + (size_t)r * D * K;
#pragma unroll
    for (int i = ty; i < 32; i += 8)
        tile[i][tx] = Wr[(size_t)(k0 + i) * D + nb + tx];
    __syncthreads();
    int gl = tx >> 4, p = tx & 15;
    int kl = (p & 3) * 4 + (p >> 2);          // inverse of pos()
#pragma unroll
    for (int i = ty; i < 32; i += 8)
        Wtr[(size_t)(nb + i) * K + k0 + gl * 16 + p] = tile[gl * 16 + kl][i];
}

// ---------------- fused layer kernel ----------------
// 128 threads = 4 warps, each warp computes full 64 rows x 64 cols (warp_n = wid).
// GEMM1: Htile(smem) = relu(gather(par->g_store)[64xK1] @ W1[r] + b1)
// GEMM2: g_store[N0+l*NL + m] = Htile @ W2[r] + b2
__global__ void __launch_bounds__(128, 1)
layer_fused(const float* __restrict__ b1, const float* __restrict__ b2,
            const int* __restrict__ par, int layer) {
    extern __shared__ float smf[];
    const uint32_t smem_u32 = smem_to_u32(smf);

    const int tid  = threadIdx.x;
    const int lane = tid & 31;
    const int wid  = tid >> 5;                // warp_n
    const int g    = lane >> 2, t4 = lane & 3;
    const int m0 = blockIdx.x * 64;
    const int r  = m0 >> 9;

    // ---- loader thread constants: 2 A chunks per thread (rows ar0, ar0+32) ----
    const int ar0 = tid >> 2;        // 0..31
    const int ar1 = ar0 + 32;
    const int sub = tid & 3;         // 4-float chunk within 16
    int p0a = par[2 * (m0 + ar0)],  p1a = par[2 * (m0 + ar0) + 1];
    int p0b = par[2 * (m0 + ar1)],  p1b = par[2 * (m0 + ar1) + 1];
    const float* asrc0a = g_store + (size_t)p0a * D;
    const float* asrc1a = g_store + (size_t)p1a * D;
    const float* asrc0b = g_store + (size_t)p0b * D;
    const float* asrc1b = g_store + (size_t)p1b * D;
    const float* W1r = g_Wt1 + (size_t)r * D * K1;
    const float* W2r = g_Wt2 + (size_t)r * D * K2;

    auto loadA = [&](int s, float4* v) {
        int gk = s * 16 + sub * 4;
        const float* sa = (gk < D) ? (asrc0a + gk) : (asrc1a + gk - D);
        const float* sb = (gk < D) ? (asrc0b + gk) : (asrc1b + gk - D);
        v[0] = *(const float4*)sa;
        v[1] = *(const float4*)sb;
    };
    auto stsA = [&](int s, const float4* v) {
        float* d0 = smf + OFF_A1 + (s & 3) * 1024 + ar0 * 16 + sub;
        d0[0] = v[0].x; d0[4] = v[0].y; d0[8] = v[0].z; d0[12] = v[0].w;
        float* d1 = smf + OFF_A1 + (s & 3) * 1024 + ar1 * 16 + sub;
        d1[0] = v[1].x; d1[4] = v[1].y; d1[8] = v[1].z; d1[12] = v[1].w;
    };
    auto issueB = [&](int bufFloats, const float* Wtr, int Kd, int s) {
#pragma unroll
        for (int j = 0; j < 8; j++) {
            int row = ar0 + 32 * j;
            const float* src = Wtr + (size_t)row * Kd + s * 16 + sub * 4;
            uint32_t dst = smem_u32 +
                (uint32_t)(bufFloats + (s & 3) * 4096 + row * 16 + sub * 4) * 4u;
            asm volatile("cp.async.cg.shared.global [%0], [%1], 16;" :: "r"(dst), "l"(src));
        }
    };

    float acc[4][8][4];
#pragma unroll
    for (int mt = 0; mt < 4; mt++)
#pragma unroll
        for (int nt = 0; nt < 8; nt++)
#pragma unroll
            for (int c = 0; c < 4; c++) acc[mt][nt][c] = 0.f;

    // fragment compute on one 16-k stage; warp tile 64x64.
    auto tile_mma = [&](const float* Abase, int astr, const float* Bbase) {
        float4 Ar[4][2];
        float4 Br[8];
#pragma unroll
        for (int mt = 0; mt < 4; mt++)
#pragma unroll
            for (int h = 0; h < 2; h++)
                Ar[mt][h] = *(const float4*)(Abase + (mt * 16 + h * 8) * astr);
#pragma unroll
        for (int nt = 0; nt < 8; nt++)
            Br[nt] = *(const float4*)(Bbase + nt * 8 * 16);
#pragma unroll
        for (int h = 0; h < 2; h++) {
#pragma unroll
            for (int mt = 0; mt < 4; mt++) {
                uint32_t a0, a1, a2, a3;
                if (h == 0) {
                    a0 = __float_as_uint(Ar[mt][0].x); a1 = __float_as_uint(Ar[mt][1].x);
                    a2 = __float_as_uint(Ar[mt][0].y); a3 = __float_as_uint(Ar[mt][1].y);
                } else {
                    a0 = __float_as_uint(Ar[mt][0].z); a1 = __float_as_uint(Ar[mt][1].z);
                    a2 = __float_as_uint(Ar[mt][0].w); a3 = __float_as_uint(Ar[mt][1].w);
                }
#pragma unroll
                for (int nt = 0; nt < 8; nt++) {
                    uint32_t b0, b1;
                    if (h == 0) { b0 = __float_as_uint(Br[nt].x); b1 = __float_as_uint(Br[nt].y); }
                    else        { b0 = __float_as_uint(Br[nt].z); b1 = __float_as_uint(Br[nt].w); }
                    asm volatile(
                        "mma.sync.aligned.m16n8k8.row.col.f32.tf32.tf32.f32 "
                        "{%0,%1,%2,%3}, {%4,%5,%6,%7}, {%8,%9}, {%0,%1,%2,%3};"
                        : "+f"(acc[mt][nt][0]), "+f"(acc[mt][nt][1]),
                          "+f"(acc[mt][nt][2]), "+f"(acc[mt][nt][3])
                        : "r"(a0), "r"(a1), "r"(a2), "r"(a3), "r"(b0), "r"(b1));
                }
            }
        }
    };

    // ================= GEMM1 =================
    {
        float4 a0[2], a1[2], a2[2];
        loadA(0, a0); loadA(1, a1); loadA(2, a2);
        issueB(OFF_B1, W1r, K1, 0); asm volatile("cp.async.commit_group;");
        issueB(OFF_B1, W1r, K1, 1); asm volatile("cp.async.commit_group;");
        issueB(OFF_B1, W1r, K1, 2); asm volatile("cp.async.commit_group;");
        stsA(0, a0); stsA(1, a1); stsA(2, a2);
        float4 aReg[2];
        loadA(3, aReg);

        for (int it = 0; it < NIT1; it++) {
            asm volatile("cp.async.wait_group 2;");
            __syncthreads();
            if (it + 3 < NIT1) {
                issueB(OFF_B1, W1r, K1, it + 3);
                asm volatile("cp.async.commit_group;");
                stsA(it + 3, aReg);
                if (it + 4 < NIT1) loadA(it + 4, aReg);
            }
            const float* Abase = smf + OFF_A1 + (it & 3) * 1024 + g * 16 + t4 * 4;
            const float* Bbase = smf + OFF_B1 + (it & 3) * 4096
                               + (wid * 64 + g) * 16 + t4 * 4;
            tile_mma(Abase, 16, Bbase);
        }
    }

    // ---- prefetch GEMM2 B stages (hidden behind H epilogue) ----
    issueB(OFF_B2, W2r, K2, 0); asm volatile("cp.async.commit_group;");
    issueB(OFF_B2, W2r, K2, 1); asm volatile("cp.async.commit_group;");
    issueB(OFF_B2, W2r, K2, 2); asm volatile("cp.async.commit_group;");

    // ---- H epilogue: bias1 + relu, scatter into interleaved H (stride 272) ----
    {
        const float* b1r = b1 + r * D;
#pragma unroll
        for (int mt = 0; mt < 4; mt++) {
            int rA = mt * 16 + g;
            int rB = rA + 8;
#pragma unroll
            for (int nt = 0; nt < 8; nt++) {
                int col0 = wid * 64 + nt * 8 + 2 * t4;
                int col1 = col0 + 1;
                float bx = b1r[col0], by = b1r[col1];
                int q0 = (col0 >> 4) * 16 + (col0 & 3) * 4 + ((col0 & 15) >> 2);
                int q1 = (col1 >> 4) * 16 + (col1 & 3) * 4 + ((col1 & 15) >> 2);
                smf[OFF_H + rA * 272 + q0] = fmaxf(acc[mt][nt][0] + bx, 0.f);
                smf[OFF_H + rA * 272 + q1] = fmaxf(acc[mt][nt][1] + by, 0.f);
                smf[OFF_H + rB * 272 + q0] = fmaxf(acc[mt][nt][2] + bx, 0.f);
                smf[OFF_H + rB * 272 + q1] = fmaxf(acc[mt][nt][3] + by, 0.f);
            }
        }
    }
    __syncthreads();

    // ================= GEMM2 (A = H resident in smem) =================
#pragma unroll
    for (int mt = 0; mt < 4; mt++)
#pragma unroll
        for (int nt = 0; nt < 8; nt++)
#pragma unroll
            for (int c = 0; c < 4; c++) acc[mt][nt][c] = 0.f;

    for (int it = 0; it < NIT2; it++) {
        asm volatile("cp.async.wait_group 2;");
        __syncthreads();
        if (it + 3 < NIT2) {
            issueB(OFF_B2, W2r, K2, it + 3);
            asm volatile("cp.async.commit_group;");
        }
        const float* Abase = smf + OFF_H + g * 272 + it * 16 + t4 * 4;
        const float* Bbase = smf + OFF_B2 + (it & 3) * 4096
                           + (wid * 64 + g) * 16 + t4 * 4;
        tile_mma(Abase, 272, Bbase);
    }

    // ---- final epilogue: bias2, write g_store ----
    {
        float* Cbase = g_store + (size_t)(N0 + layer * NL) * D;
        const float* b2r = b2 + r * D;
#pragma unroll
        for (int mt = 0; mt < 4; mt++) {
            int mr0 = m0 + mt * 16 + g;
#pragma unroll
            for (int nt = 0; nt < 8; nt++) {
                int col = wid * 64 + nt * 8 + 2 * t4;
                float bx = b2r[col], by = b2r[col + 1];
                float2 v0, v1;
                v0.x = acc[mt][nt][0] + bx;  v0.y = acc[mt][nt][1] + by;
                v1.x = acc[mt][nt][2] + bx;  v1.y = acc[mt][nt][3] + by;
                *(float2*)(Cbase + (size_t)mr0 * D + col)       = v0;
                *(float2*)(Cbase + (size_t)(mr0 + 8) * D + col) = v1;
            }
        }
    }
}

// ---------------- eval + loss (deterministic two-stage reduction) ----------------
__device__ __forceinline__ float softplusf(float x) {
    return fmaxf(x, 0.f) + log1pf(expf(-fabsf(x)));
}

__global__ void __launch_bounds__(256)
eval_partial(const float* __restrict__ pos_vals, const float* __restrict__ neg_vals,
             const float* __restrict__ eval_w, const float* __restrict__ eval_b,
             const float* __restrict__ pos_weight) {
    __shared__ float red[8][5];
    const int lane = threadIdx.x & 31, warp = threadIdx.x >> 5;
    const int gw = blockIdx.x * 8 + warp;

    float w[8];
#pragma unroll
    for (int j = 0; j < 8; j++) w[j] = eval_w[lane + 32 * j];
    const float eb = *eval_b;
    const float pw = *pos_weight;

    float loss = 0.f, posOK = 0.f, negOK = 0.f, posTot = 0.f, negTot = 0.f;

    for (int node = gw; node < TOTAL; node += EVAL_BLOCKS * 8) {
        const float* row = g_store + (size_t)node * D;
        float s = 0.f;
#pragma unroll
        for (int j = 0; j < 8; j++) s += row[lane + 32 * j] * w[j];
#pragma unroll
        for (int off = 16; off; off >>= 1) s += __shfl_xor_sync(0xffffffffu, s, off);
        if (lane == 0) {
            float x = s + eb;
            float pv = pos_vals[node], nv = neg_vals[node];
            float tot = pv + nv;
            if (tot > 0.f) {
                float tgt = pv / fmaxf(tot, 1e-9f);
                float bce = pw * tgt * softplusf(-x) + (1.f - tgt) * softplusf(x);
                loss += tot * bce;
                posTot += pv; negTot += nv;
                if (x >= 0.f) posOK += pv; else negOK += nv;
            }
        }
    }
    if (lane == 0) {
        red[warp][0] = loss; red[warp][1] = posOK; red[warp][2] = negOK;
        red[warp][3] = posTot; red[warp][4] = negTot;
    }
    __syncthreads();
    if (threadIdx.x < 5) {
        float t = 0.f;
        for (int i = 0; i < 8; i++) t += red[i][threadIdx.x];
        g_partials[blockIdx.x * 5 + threadIdx.x] = t;
    }
}

__global__ void final_reduce(float* __restrict__ out, int out_size) {
    float s[5] = {0.f, 0.f, 0.f, 0.f, 0.f};
    for (int i = threadIdx.x; i < EVAL_BLOCKS; i += 32)
#pragma unroll
        for (int c = 0; c < 5; c++) s[c] += g_partials[i * 5 + c];
#pragma unroll
    for (int c = 0; c < 5; c++)
#pragma unroll
        for (int off = 16; off; off >>= 1)
            s[c] += __shfl_xor_sync(0xffffffffu, s[c], off);
    if (threadIdx.x == 0) {
        float loss = s[0], posOK = s[1], negOK = s[2], posTot = s[3], negTot = s[4];
        float pos_rate = (posTot > 0.f) ? posOK / fmaxf(posTot, 1e-9f) : 1.f;
        float neg_rate = (negTot > 0.f) ? negOK / fmaxf(negTot, 1e-9f) : 1.f;
        if (out_size >= 1) out[0] = loss;
        if (out_size >= 2) out[1] = pos_rate;
        if (out_size >= 3) out[2] = neg_rate;
    }
}

// ---------------- launch ----------------
extern "C" void kernel_launch(void* const* d_in, const int* in_sizes, int n_in,
                              void* d_out, int out_size) {
    const int*   thax       = (const int*)  d_in[0];
    const int*   par_idx    = (const int*)  d_in[1];
    const float* pos_vals   = (const float*)d_in[2];
    const float* neg_vals   = (const float*)d_in[3];
    const float* init_table = (const float*)d_in[4];
    const float* W1         = (const float*)d_in[5];
    const float* b1         = (const float*)d_in[6];
    const float* W2         = (const float*)d_in[7];
    const float* b2         = (const float*)d_in[8];
    const float* eval_w     = (const float*)d_in[9];
    const float* eval_b     = (const float*)d_in[10];
    const float* pos_weight = (const float*)d_in[11];
    float* out = (float*)d_out;

    cudaFuncSetAttribute(layer_fused,
                         cudaFuncAttributeMaxDynamicSharedMemorySize, SMEM_BYTES);

    init_gather<<<(N0 * 64) / 256, 256>>>(thax, init_table);
    transpose_w<K1, true ><<<dim3(K1 / 32, D / 32, R), dim3(32, 8)>>>(W1);
    transpose_w<K2, false><<<dim3(K2 / 32, D / 32, R), dim3(32, 8)>>>(W2);

    for (int l = 0; l < L; l++) {
        layer_fused<<<NL / 64, 128, SMEM_BYTES>>>(
            b1, b2, par_idx + (size_t)l * NL * 2, l);
    }

    eval_partial<<<EVAL_BLOCKS, 256>>>(pos_vals, neg_vals, eval_w, eval_b, pos_weight);
    final_reduce<<<1, 32>>>(out, out_size);
}